// round 9
// baseline (speedup 1.0000x reference)
#include <cuda_runtime.h>

typedef unsigned long long u64;

#define BT  256   // threads per block
#define XPT 4     // vectors per thread
#define NP  128   // codeword pairs

__device__    u64 g_q[NP];   // packed ||c||^2 per pair (staging)
__constant__  u64 c_q[NP];   // same, in the constant bank (separate LDC port)

__device__ __forceinline__ u64 pk2(float lo, float hi) {
    u64 r;
    asm("mov.b64 %0, {%1, %2};" : "=l"(r) : "f"(lo), "f"(hi));
    return r;
}
__device__ __forceinline__ void upk2(u64 v, float& lo, float& hi) {
    asm("mov.b64 {%0, %1}, %2;" : "=f"(lo), "=f"(hi) : "l"(v));
}
// Blackwell packed fp32 FMA: d.lo = a.lo*b.lo + c.lo ; d.hi = a.hi*b.hi + c.hi
__device__ __forceinline__ u64 ffma2(u64 a, u64 b, u64 c) {
    u64 d;
    asm("fma.rn.f32x2 %0, %1, %2, %3;" : "=l"(d) : "l"(a), "l"(b), "l"(c));
    return d;
}

__global__ void pack_q(const float4* __restrict__ C) {
    const int t = threadIdx.x;
    if (t < NP) {
        float4 a = C[2 * t];
        float4 b = C[2 * t + 1];
        float qa = a.x * a.x + a.y * a.y + a.z * a.z + a.w * a.w;
        float qb = b.x * b.x + b.y * b.y + b.z * b.z + b.w * b.w;
        g_q[t] = pk2(qa, qb);
    }
}

struct VState {
    u64 y0[XPT], y1[XPT], y2[XPT], y3[XPT];
    float bv[XPT];
    int   pid[XPT];
};

// One codeword pair against all XPT vectors.
__device__ __forceinline__ void do_pair(VState& s, const ulonglong2* sAB,
                                        const ulonglong2* sCD, int p)
{
    const ulonglong2 ab = sAB[p];    // broadcast LDS, conflict-free
    const ulonglong2 cd = sCD[p];
    const u64        q  = c_q[p];    // uniform LDC, constant port
#pragma unroll
    for (int j = 0; j < XPT; j++) {
        u64 acc = ffma2(s.y0[j], ab.x, q);
        acc = ffma2(s.y1[j], ab.y, acc);
        acc = ffma2(s.y2[j], cd.x, acc);
        acc = ffma2(s.y3[j], cd.y, acc);
        float lo, hi;
        upk2(acc, lo, hi);
        float pv = fminf(lo, hi);
        if (pv < s.bv[j]) s.pid[j] = p;   // strict <: earlier-seen wins exact ties
        s.bv[j] = fminf(s.bv[j], pv);     // FMNMX chain, lat 4
    }
}

__global__ void __launch_bounds__(BT, 4)
vq_kernel(const float4* __restrict__ X,
          const float4* __restrict__ C,
          float4* __restrict__ outX,
          float* __restrict__ outS,
          int B)
{
    __shared__ ulonglong2 sAB[NP];   // (dim0 pair, dim1 pair)
    __shared__ ulonglong2 sCD[NP];   // (dim2 pair, dim3 pair)

    const int t = threadIdx.x;

    if (t < NP) {
        float4 a = C[2 * t];
        float4 b = C[2 * t + 1];
        sAB[t] = make_ulonglong2(pk2(a.x, b.x), pk2(a.y, b.y));
        sCD[t] = make_ulonglong2(pk2(a.z, b.z), pk2(a.w, b.w));
    }
    __syncthreads();

    const int base = blockIdx.x * (BT * XPT) + t;

    VState s;
#pragma unroll
    for (int j = 0; j < XPT; j++) {
        int idx = base + j * BT;
        float4 x = (idx < B) ? X[idx] : make_float4(0.f, 0.f, 0.f, 0.f);
        float m0 = -2.0f * x.x, m1 = -2.0f * x.y, m2 = -2.0f * x.z, m3 = -2.0f * x.w;
        s.y0[j] = pk2(m0, m0);
        s.y1[j] = pk2(m1, m1);
        s.y2[j] = pk2(m2, m2);
        s.y3[j] = pk2(m3, m3);
        s.bv[j] = 3.402823466e38f;
        s.pid[j] = 0;
    }

    // Staggered sweep: warp w starts at pair 16*(w&7) so warps never hit the same
    // smem line in the same cycle (decorrelates LDS bursts across the SM).
    const int start = ((t >> 5) & 7) << 4;

#pragma unroll 4
    for (int p = start; p < NP; p++) do_pair(s, sAB, sCD, p);
#pragma unroll 4
    for (int p = 0; p < start; p++) do_pair(s, sAB, sCD, p);

    // Recovery: replay the winning pair's bitwise-identical FFMA2 chain (2 divergent
    // LDS + 1 divergent LDC per vector, once). FMNMX returns an input exactly, so
    // hi<lo resolves the within-pair index; ties prefer lo (= smaller index),
    // matching jnp.argmin. Winner components come from pair registers via SELs.
#pragma unroll
    for (int j = 0; j < XPT; j++) {
        const int p = s.pid[j];
        const ulonglong2 rab = sAB[p];
        const ulonglong2 rcd = sCD[p];
        const u64        rq  = c_q[p];
        u64 acc = ffma2(s.y0[j], rab.x, rq);
        acc = ffma2(s.y1[j], rab.y, acc);
        acc = ffma2(s.y2[j], rcd.x, acc);
        acc = ffma2(s.y3[j], rcd.y, acc);
        float lo, hi;
        upk2(acc, lo, hi);
        const bool h = (hi < lo);
        float a0, b0, a1, b1, a2, b2, a3, b3;
        upk2(rab.x, a0, b0); upk2(rab.y, a1, b1);
        upk2(rcd.x, a2, b2); upk2(rcd.y, a3, b3);
        const int idx = base + j * BT;
        if (idx < B) {
            outX[idx] = make_float4(h ? b0 : a0, h ? b1 : a1,
                                    h ? b2 : a2, h ? b3 : a3);
            outS[idx] = (float)(2 * p + (h ? 1 : 0));   // harness reads d_out as f32
        }
    }
}

extern "C" void kernel_launch(void* const* d_in, const int* in_sizes, int n_in,
                              void* d_out, int out_size)
{
    const float4* X = (const float4*)d_in[0];   // [B, 4] fp32
    const float4* C = (const float4*)d_in[1];   // [256, 4] fp32 codebook

    const int B = in_sizes[0] / 4;

    float4* outX = (float4*)d_out;                  // hatX [B,4] fp32
    float*  outS = (float*)d_out + 4 * (size_t)B;   // state [B] as fp32

    // Stage packed ||c||^2 into the constant bank (all capturable, D2D only).
    pack_q<<<1, 128>>>(C);
    void* gp = nullptr;
    cudaGetSymbolAddress(&gp, g_q);
    cudaMemcpyToSymbolAsync(c_q, gp, sizeof(u64) * NP, 0,
                            cudaMemcpyDeviceToDevice, 0);

    const int grid = (B + BT * XPT - 1) / (BT * XPT);
    vq_kernel<<<grid, BT>>>(X, C, outX, outS, B);
}